// round 1
// baseline (speedup 1.0000x reference)
#include <cuda_runtime.h>
#include <cuda_bf16.h>
#include <cstdint>

// Problem constants
#define BATCH 4
#define SEQ   2048
#define EMB   1024
#define HEADS 16
#define HDIM  64
#define MDIM  (BATCH * SEQ)   // 8192
#define SCALING 0.125f        // 64^-0.5

// Scratch (no allocation allowed) — [B,H,S,D] layouts for Q/K/V, [B,S,E] for attn out
__device__ float g_Q[(size_t)BATCH * HEADS * SEQ * HDIM];
__device__ float g_K[(size_t)BATCH * HEADS * SEQ * HDIM];
__device__ float g_V[(size_t)BATCH * HEADS * SEQ * HDIM];
__device__ float g_attn[(size_t)BATCH * SEQ * EMB];

// ---------------------------------------------------------------------------
// GEMM: out[m,n] = sum_k A[m,k] * W[n,k] + bias[n]
// which 0/1/2: out scattered into g_Q/g_K/g_V as [B,H,S,D]
// which 3:     A = g_attn, out = outp plain [M,N]
// Tiles: 128x128x16, 256 threads, 8x8 per-thread microtile.
// ---------------------------------------------------------------------------
__global__ __launch_bounds__(256, 2)
void gemm_kernel(const float* __restrict__ Ain, const float* __restrict__ W,
                 const float* __restrict__ bias, float* __restrict__ outp,
                 int which)
{
    constexpr int BK = 16;
    __shared__ float As[BK][128];
    __shared__ float Bs[BK][128];

    const int tid = threadIdx.x;
    const int bm = blockIdx.y * 128;
    const int bn = blockIdx.x * 128;

    const float* A = (which == 3) ? g_attn : Ain;

    // gmem->smem mapping: each thread loads 8 A floats + 8 W floats per k-tile
    const int lrow = tid >> 1;          // 0..127
    const int lk   = (tid & 1) * 8;     // 0 or 8

    // compute mapping: 8 warps as 4(m) x 2(n); lane 4(m) x 8(n)
    const int w    = tid >> 5;
    const int lane = tid & 31;
    const int tm   = (w >> 1) * 32 + (lane >> 3) * 8;
    const int tn   = (w & 1) * 64 + (lane & 7) * 8;

    float acc[8][8];
    #pragma unroll
    for (int i = 0; i < 8; i++)
        #pragma unroll
        for (int j = 0; j < 8; j++) acc[i][j] = 0.f;

    const float* Arow = A + (size_t)(bm + lrow) * EMB + lk;
    const float* Wrow = W + (size_t)(bn + lrow) * EMB + lk;

    for (int k0 = 0; k0 < EMB; k0 += BK) {
        float4 a0 = *(const float4*)(Arow + k0);
        float4 a1 = *(const float4*)(Arow + k0 + 4);
        float4 b0 = *(const float4*)(Wrow + k0);
        float4 b1 = *(const float4*)(Wrow + k0 + 4);
        As[lk + 0][lrow] = a0.x; As[lk + 1][lrow] = a0.y;
        As[lk + 2][lrow] = a0.z; As[lk + 3][lrow] = a0.w;
        As[lk + 4][lrow] = a1.x; As[lk + 5][lrow] = a1.y;
        As[lk + 6][lrow] = a1.z; As[lk + 7][lrow] = a1.w;
        Bs[lk + 0][lrow] = b0.x; Bs[lk + 1][lrow] = b0.y;
        Bs[lk + 2][lrow] = b0.z; Bs[lk + 3][lrow] = b0.w;
        Bs[lk + 4][lrow] = b1.x; Bs[lk + 5][lrow] = b1.y;
        Bs[lk + 6][lrow] = b1.z; Bs[lk + 7][lrow] = b1.w;
        __syncthreads();

        #pragma unroll
        for (int kk = 0; kk < BK; kk++) {
            float af[8], bf[8];
            *(float4*)&af[0] = *(const float4*)&As[kk][tm];
            *(float4*)&af[4] = *(const float4*)&As[kk][tm + 4];
            *(float4*)&bf[0] = *(const float4*)&Bs[kk][tn];
            *(float4*)&bf[4] = *(const float4*)&Bs[kk][tn + 4];
            #pragma unroll
            for (int i = 0; i < 8; i++)
                #pragma unroll
                for (int j = 0; j < 8; j++)
                    acc[i][j] += af[i] * bf[j];
        }
        __syncthreads();
    }

    const int n0 = bn + tn;
    float bsv[8];
    #pragma unroll
    for (int j = 0; j < 8; j++) bsv[j] = bias[n0 + j];

    if (which <= 2) {
        float* dst = (which == 0) ? g_Q : (which == 1) ? g_K : g_V;
        const int h  = n0 >> 6;      // 8-col span stays within one head (tn 8-aligned, 64-blocked)
        const int d0 = n0 & 63;
        #pragma unroll
        for (int i = 0; i < 8; i++) {
            const int m = bm + tm + i;
            const int b = m >> 11;        // m / 2048
            const int srow = m & 2047;
            float* orow = dst + (((size_t)(b * HEADS + h) * SEQ + srow) * HDIM + d0);
            float4 v0, v1;
            v0.x = acc[i][0] + bsv[0]; v0.y = acc[i][1] + bsv[1];
            v0.z = acc[i][2] + bsv[2]; v0.w = acc[i][3] + bsv[3];
            v1.x = acc[i][4] + bsv[4]; v1.y = acc[i][5] + bsv[5];
            v1.z = acc[i][6] + bsv[6]; v1.w = acc[i][7] + bsv[7];
            ((float4*)orow)[0] = v0;
            ((float4*)orow)[1] = v1;
        }
    } else {
        #pragma unroll
        for (int i = 0; i < 8; i++) {
            const int m = bm + tm + i;
            float* orow = outp + (size_t)m * EMB + n0;
            float4 v0, v1;
            v0.x = acc[i][0] + bsv[0]; v0.y = acc[i][1] + bsv[1];
            v0.z = acc[i][2] + bsv[2]; v0.w = acc[i][3] + bsv[3];
            v1.x = acc[i][4] + bsv[4]; v1.y = acc[i][5] + bsv[5];
            v1.z = acc[i][6] + bsv[6]; v1.w = acc[i][7] + bsv[7];
            ((float4*)orow)[0] = v0;
            ((float4*)orow)[1] = v1;
        }
    }
}

// ---------------------------------------------------------------------------
// Flash attention (fp32, online softmax). One query row per thread.
// grid: (SEQ/128, B*H), block: 128 threads.
// Writes g_attn in [B,S,E] layout (E index = h*64 + d).
// ---------------------------------------------------------------------------
__global__ __launch_bounds__(128)
void attn_kernel()
{
    __shared__ float Ks[32][64];
    __shared__ float Vs[32][64];

    const int bh  = blockIdx.y;                       // 0..63
    const int row = blockIdx.x * 128 + threadIdx.x;   // query row in [0,2048)

    const float* qp = g_Q + ((size_t)bh * SEQ + row) * HDIM;
    float q[64];
    #pragma unroll
    for (int i = 0; i < 16; i++) {
        float4 t = ((const float4*)qp)[i];
        q[4*i+0] = t.x; q[4*i+1] = t.y; q[4*i+2] = t.z; q[4*i+3] = t.w;
    }

    float o[64];
    #pragma unroll
    for (int i = 0; i < 64; i++) o[i] = 0.f;
    float mx = -1e30f, l = 0.f;

    const float4* kbase = (const float4*)(g_K + (size_t)bh * SEQ * HDIM);
    const float4* vbase = (const float4*)(g_V + (size_t)bh * SEQ * HDIM);
    float4* Ks4 = (float4*)&Ks[0][0];
    float4* Vs4 = (float4*)&Vs[0][0];

    for (int t0 = 0; t0 < SEQ; t0 += 32) {
        // cooperatively load K/V tile (32 rows x 64 floats = 512 float4 each)
        const float4* ksrc = kbase + (size_t)t0 * 16;
        const float4* vsrc = vbase + (size_t)t0 * 16;
        #pragma unroll
        for (int i = 0; i < 4; i++) {
            int idx = threadIdx.x + 128 * i;
            Ks4[idx] = ksrc[idx];
            Vs4[idx] = vsrc[idx];
        }
        __syncthreads();

        float s[32];
        #pragma unroll 4
        for (int j = 0; j < 32; j++) {
            float a0 = 0.f, a1 = 0.f, a2 = 0.f, a3 = 0.f;
            const float4* kr = (const float4*)&Ks[j][0];
            #pragma unroll
            for (int k4 = 0; k4 < 16; k4++) {
                float4 kv = kr[k4];
                a0 += q[4*k4+0] * kv.x;
                a1 += q[4*k4+1] * kv.y;
                a2 += q[4*k4+2] * kv.z;
                a3 += q[4*k4+3] * kv.w;
            }
            s[j] = (a0 + a1 + a2 + a3) * SCALING;
        }

        float tmax = mx;
        #pragma unroll
        for (int j = 0; j < 32; j++) tmax = fmaxf(tmax, s[j]);
        const float corr = __expf(mx - tmax);
        mx = tmax;
        l *= corr;
        #pragma unroll
        for (int d = 0; d < 64; d++) o[d] *= corr;
        #pragma unroll
        for (int j = 0; j < 32; j++) {
            s[j] = __expf(s[j] - tmax);
            l += s[j];
        }

        #pragma unroll 4
        for (int j = 0; j < 32; j++) {
            const float p = s[j];
            const float4* vr = (const float4*)&Vs[j][0];
            #pragma unroll
            for (int d4 = 0; d4 < 16; d4++) {
                float4 vv = vr[d4];
                o[4*d4+0] += p * vv.x;
                o[4*d4+1] += p * vv.y;
                o[4*d4+2] += p * vv.z;
                o[4*d4+3] += p * vv.w;
            }
        }
        __syncthreads();
    }

    const float inv = 1.f / l;
    const int b = bh >> 4;
    const int h = bh & 15;
    float* op = g_attn + ((size_t)b * SEQ + row) * EMB + h * HDIM;
    #pragma unroll
    for (int i = 0; i < 16; i++) {
        float4 v;
        v.x = o[4*i+0] * inv; v.y = o[4*i+1] * inv;
        v.z = o[4*i+2] * inv; v.w = o[4*i+3] * inv;
        ((float4*)op)[i] = v;
    }
}

// ---------------------------------------------------------------------------
// Launch
// ---------------------------------------------------------------------------
extern "C" void kernel_launch(void* const* d_in, const int* in_sizes, int n_in,
                              void* d_out, int out_size)
{
    const float* query = (const float*)d_in[0];
    const float* key   = (const float*)d_in[1];
    const float* value = (const float*)d_in[2];
    const float* q_w   = (const float*)d_in[3];
    const float* q_b   = (const float*)d_in[4];
    const float* k_w   = (const float*)d_in[5];
    const float* k_b   = (const float*)d_in[6];
    const float* v_w   = (const float*)d_in[7];
    const float* v_b   = (const float*)d_in[8];
    const float* out_w = (const float*)d_in[9];
    const float* out_b = (const float*)d_in[10];
    float* out = (float*)d_out;

    dim3 ggrid(EMB / 128, MDIM / 128);   // (8, 64)
    gemm_kernel<<<ggrid, 256>>>(query, q_w, q_b, nullptr, 0);
    gemm_kernel<<<ggrid, 256>>>(key,   k_w, k_b, nullptr, 1);
    gemm_kernel<<<ggrid, 256>>>(value, v_w, v_b, nullptr, 2);

    attn_kernel<<<dim3(SEQ / 128, BATCH * HEADS), 128>>>();

    gemm_kernel<<<ggrid, 256>>>(nullptr, out_w, out_b, out, 3);
}

// round 7
// speedup vs baseline: 1.3718x; 1.3718x over previous
#include <cuda_runtime.h>
#include <cuda_bf16.h>
#include <cstdint>

// Problem constants
#define BATCH 4
#define SEQ   2048
#define EMB   1024
#define HEADS 16
#define HDIM  64
#define MDIM  (BATCH * SEQ)   // 8192
#define SCALING 0.125f        // 64^-0.5

// Scratch — [B,H,S,D] layouts for Q/K/V, [B,S,E] for attn out
__device__ float g_Q[(size_t)BATCH * HEADS * SEQ * HDIM];
__device__ float g_K[(size_t)BATCH * HEADS * SEQ * HDIM];
__device__ float g_V[(size_t)BATCH * HEADS * SEQ * HDIM];
__device__ float g_attn[(size_t)BATCH * SEQ * EMB];

// ---------------------------------------------------------------------------
// mma.sync tf32 GEMM: out[m,n] = sum_k A[m,k]*W[n,k] + bias[n]
// 128x128x32 tiles, 256 threads = 8 warps as 2(m) x 4(n), warp tile 64x32.
// m16n8k8 fragments loaded from padded smem (stride 36 words -> conflict-free).
// which 0/1/2: scatter into g_Q/g_K/g_V as [B,H,S,D]; which 3: plain [M,N].
// ---------------------------------------------------------------------------
#define BK   32
#define PAD  36                         // padded row stride in words
#define STAGE_WORDS (128 * PAD)         // one operand stage
#define GEMM_SMEM (4 * STAGE_WORDS * 4) // A0,A1,B0,B1 = 73728 bytes

__device__ __forceinline__ uint32_t cvt_tf32(float x) {
    uint32_t r;
    asm("cvt.rna.tf32.f32 %0, %1;" : "=r"(r) : "f"(x));
    return r;
}

__device__ __forceinline__ void mma_16x8x8(float* c, const uint32_t* a, const uint32_t* b) {
    asm volatile(
        "mma.sync.aligned.m16n8k8.row.col.f32.tf32.tf32.f32 "
        "{%0,%1,%2,%3}, {%4,%5,%6,%7}, {%8,%9}, {%0,%1,%2,%3};"
        : "+f"(c[0]), "+f"(c[1]), "+f"(c[2]), "+f"(c[3])
        : "r"(a[0]), "r"(a[1]), "r"(a[2]), "r"(a[3]), "r"(b[0]), "r"(b[1]));
}

__global__ __launch_bounds__(256, 1)
void gemm_mma(const float* __restrict__ Ain, const float* __restrict__ W,
              const float* __restrict__ bias, float* __restrict__ outp, int which)
{
    extern __shared__ uint32_t sm[];
    uint32_t* As = sm;                      // [2][128][PAD]
    uint32_t* Bs = sm + 2 * STAGE_WORDS;    // [2][128][PAD]

    const int tid  = threadIdx.x;
    const int warp = tid >> 5, lane = tid & 31;
    const int g = lane >> 2, t = lane & 3;       // group row, thread-in-group
    const int wm = warp >> 2, wn = warp & 3;     // warp tile coords
    const int bm = blockIdx.y * 128, bn = blockIdx.x * 128;
    const float* A = (which == 3) ? g_attn : Ain;

    // gmem load mapping: 4 float4 each from A and W per k-tile
    // float4 linear index l = tid + 256*i -> row = l>>3, c4 = l&7
    float4 ra[4], rb[4];
    #pragma unroll
    for (int i = 0; i < 4; i++) {
        const int l = tid + 256 * i, row = l >> 3, c4 = l & 7;
        ra[i] = *(const float4*)(A + (size_t)(bm + row) * EMB + c4 * 4);
        rb[i] = *(const float4*)(W + (size_t)(bn + row) * EMB + c4 * 4);
    }
    #pragma unroll
    for (int i = 0; i < 4; i++) {
        const int l = tid + 256 * i, row = l >> 3, c4 = l & 7;
        uint32_t* pa = As + row * PAD + c4 * 4;
        uint32_t* pb = Bs + row * PAD + c4 * 4;
        pa[0] = cvt_tf32(ra[i].x); pa[1] = cvt_tf32(ra[i].y);
        pa[2] = cvt_tf32(ra[i].z); pa[3] = cvt_tf32(ra[i].w);
        pb[0] = cvt_tf32(rb[i].x); pb[1] = cvt_tf32(rb[i].y);
        pb[2] = cvt_tf32(rb[i].z); pb[3] = cvt_tf32(rb[i].w);
    }
    __syncthreads();

    float acc[4][4][4];
    #pragma unroll
    for (int mf = 0; mf < 4; mf++)
        #pragma unroll
        for (int nf = 0; nf < 4; nf++)
            #pragma unroll
            for (int c = 0; c < 4; c++) acc[mf][nf][c] = 0.f;

    const int NKT = EMB / BK;  // 32

    for (int kt = 0; kt < NKT; kt++) {
        const int cur = kt & 1;
        const uint32_t* Ab = As + cur * STAGE_WORDS;
        const uint32_t* Bb = Bs + cur * STAGE_WORDS;

        // prefetch next k-tile into regs
        if (kt + 1 < NKT) {
            const int k0 = (kt + 1) * BK;
            #pragma unroll
            for (int i = 0; i < 4; i++) {
                const int l = tid + 256 * i, row = l >> 3, c4 = l & 7;
                ra[i] = *(const float4*)(A + (size_t)(bm + row) * EMB + k0 + c4 * 4);
                rb[i] = *(const float4*)(W + (size_t)(bn + row) * EMB + k0 + c4 * 4);
            }
        }

        // compute: 4 k-steps of 8
        #pragma unroll
        for (int ks = 0; ks < 4; ks++) {
            const int kk = ks * 8;
            uint32_t af[4][4], bf[4][2];
            #pragma unroll
            for (int mf = 0; mf < 4; mf++) {
                const int m = wm * 64 + mf * 16;
                af[mf][0] = Ab[(m + g) * PAD + kk + t];
                af[mf][1] = Ab[(m + g + 8) * PAD + kk + t];
                af[mf][2] = Ab[(m + g) * PAD + kk + t + 4];
                af[mf][3] = Ab[(m + g + 8) * PAD + kk + t + 4];
            }
            #pragma unroll
            for (int nf = 0; nf < 4; nf++) {
                const int n = wn * 32 + nf * 8;
                bf[nf][0] = Bb[(n + g) * PAD + kk + t];
                bf[nf][1] = Bb[(n + g) * PAD + kk + t + 4];
            }
            #pragma unroll
            for (int mf = 0; mf < 4; mf++)
                #pragma unroll
                for (int nf = 0; nf < 4; nf++)
                    mma_16x8x8(acc[mf][nf], af[mf], bf[nf]);
        }

        // stage next tile
        if (kt + 1 < NKT) {
            __syncthreads();  // everyone done reading stage nxt (from kt-1)
            const int nxt = 1 - cur;
            uint32_t* Aw = As + nxt * STAGE_WORDS;
            uint32_t* Bw = Bs + nxt * STAGE_WORDS;
            #pragma unroll
            for (int i = 0; i < 4; i++) {
                const int l = tid + 256 * i, row = l >> 3, c4 = l & 7;
                uint32_t* pa = Aw + row * PAD + c4 * 4;
                uint32_t* pb = Bw + row * PAD + c4 * 4;
                pa[0] = cvt_tf32(ra[i].x); pa[1] = cvt_tf32(ra[i].y);
                pa[2] = cvt_tf32(ra[i].z); pa[3] = cvt_tf32(ra[i].w);
                pb[0] = cvt_tf32(rb[i].x); pb[1] = cvt_tf32(rb[i].y);
                pb[2] = cvt_tf32(rb[i].z); pb[3] = cvt_tf32(rb[i].w);
            }
            __syncthreads();
        }
    }

    // epilogue: c0=C[g][t2], c1=C[g][t2+1], c2=C[g+8][t2], c3=C[g+8][t2+1]
    #pragma unroll
    for (int nf = 0; nf < 4; nf++) {
        const int n = bn + wn * 32 + nf * 8 + t * 2;
        const float2 bv = *(const float2*)(bias + n);
        #pragma unroll
        for (int mf = 0; mf < 4; mf++) {
            const int m0 = bm + wm * 64 + mf * 16 + g;
            float2 v0, v1;
            v0.x = acc[mf][nf][0] + bv.x; v0.y = acc[mf][nf][1] + bv.y;
            v1.x = acc[mf][nf][2] + bv.x; v1.y = acc[mf][nf][3] + bv.y;
            if (which <= 2) {
                float* dst = (which == 0) ? g_Q : (which == 1) ? g_K : g_V;
                const int h = n >> 6, d0 = n & 63;
                const int b0r = m0 >> 11, s0 = m0 & 2047;
                const int b1r = (m0 + 8) >> 11, s1 = (m0 + 8) & 2047;
                *(float2*)(dst + (((size_t)(b0r * HEADS + h) * SEQ + s0) * HDIM + d0)) = v0;
                *(float2*)(dst + (((size_t)(b1r * HEADS + h) * SEQ + s1) * HDIM + d0)) = v1;
            } else {
                *(float2*)(outp + (size_t)m0 * EMB + n) = v0;
                *(float2*)(outp + (size_t)(m0 + 8) * EMB + n) = v1;
            }
        }
    }
}

// ---------------------------------------------------------------------------
// Flash attention (fp32, online softmax). One query row per thread.
// (R1 proven version — tensor-core port comes next round.)
// ---------------------------------------------------------------------------
__global__ __launch_bounds__(128)
void attn_kernel()
{
    __shared__ float Ks[32][64];
    __shared__ float Vs[32][64];

    const int bh  = blockIdx.y;                       // 0..63
    const int row = blockIdx.x * 128 + threadIdx.x;   // query row in [0,2048)

    const float* qp = g_Q + ((size_t)bh * SEQ + row) * HDIM;
    float q[64];
    #pragma unroll
    for (int i = 0; i < 16; i++) {
        float4 tv = ((const float4*)qp)[i];
        q[4*i+0] = tv.x; q[4*i+1] = tv.y; q[4*i+2] = tv.z; q[4*i+3] = tv.w;
    }

    float o[64];
    #pragma unroll
    for (int i = 0; i < 64; i++) o[i] = 0.f;
    float mx = -1e30f, l = 0.f;

    const float4* kbase = (const float4*)(g_K + (size_t)bh * SEQ * HDIM);
    const float4* vbase = (const float4*)(g_V + (size_t)bh * SEQ * HDIM);
    float4* Ks4 = (float4*)&Ks[0][0];
    float4* Vs4 = (float4*)&Vs[0][0];

    for (int t0 = 0; t0 < SEQ; t0 += 32) {
        const float4* ksrc = kbase + (size_t)t0 * 16;
        const float4* vsrc = vbase + (size_t)t0 * 16;
        #pragma unroll
        for (int i = 0; i < 4; i++) {
            int idx = threadIdx.x + 128 * i;
            Ks4[idx] = ksrc[idx];
            Vs4[idx] = vsrc[idx];
        }
        __syncthreads();

        float s[32];
        #pragma unroll 4
        for (int j = 0; j < 32; j++) {
            float a0 = 0.f, a1 = 0.f, a2 = 0.f, a3 = 0.f;
            const float4* kr = (const float4*)&Ks[j][0];
            #pragma unroll
            for (int k4 = 0; k4 < 16; k4++) {
                float4 kv = kr[k4];
                a0 += q[4*k4+0] * kv.x;
                a1 += q[4*k4+1] * kv.y;
                a2 += q[4*k4+2] * kv.z;
                a3 += q[4*k4+3] * kv.w;
            }
            s[j] = (a0 + a1 + a2 + a3) * SCALING;
        }

        float tmax = mx;
        #pragma unroll
        for (int j = 0; j < 32; j++) tmax = fmaxf(tmax, s[j]);
        const float corr = __expf(mx - tmax);
        mx = tmax;
        l *= corr;
        #pragma unroll
        for (int d = 0; d < 64; d++) o[d] *= corr;
        #pragma unroll
        for (int j = 0; j < 32; j++) {
            s[j] = __expf(s[j] - tmax);
            l += s[j];
        }

        #pragma unroll 4
        for (int j = 0; j < 32; j++) {
            const float p = s[j];
            const float4* vr = (const float4*)&Vs[j][0];
            #pragma unroll
            for (int d4 = 0; d4 < 16; d4++) {
                float4 vv = vr[d4];
                o[4*d4+0] += p * vv.x;
                o[4*d4+1] += p * vv.y;
                o[4*d4+2] += p * vv.z;
                o[4*d4+3] += p * vv.w;
            }
        }
        __syncthreads();
    }

    const float inv = 1.f / l;
    const int b = bh >> 4;
    const int h = bh & 15;
    float* op = g_attn + ((size_t)b * SEQ + row) * EMB + h * HDIM;
    #pragma unroll
    for (int i = 0; i < 16; i++) {
        float4 v;
        v.x = o[4*i+0] * inv; v.y = o[4*i+1] * inv;
        v.z = o[4*i+2] * inv; v.w = o[4*i+3] * inv;
        ((float4*)op)[i] = v;
    }
}

// ---------------------------------------------------------------------------
// Launch
// ---------------------------------------------------------------------------
extern "C" void kernel_launch(void* const* d_in, const int* in_sizes, int n_in,
                              void* d_out, int out_size)
{
    const float* query = (const float*)d_in[0];
    const float* key   = (const float*)d_in[1];
    const float* value = (const float*)d_in[2];
    const float* q_w   = (const float*)d_in[3];
    const float* q_b   = (const float*)d_in[4];
    const float* k_w   = (const float*)d_in[5];
    const float* k_b   = (const float*)d_in[6];
    const float* v_w   = (const float*)d_in[7];
    const float* v_b   = (const float*)d_in[8];
    const float* out_w = (const float*)d_in[9];
    const float* out_b = (const float*)d_in[10];
    float* out = (float*)d_out;

    static bool attr_set = false;
    if (!attr_set) {
        cudaFuncSetAttribute(gemm_mma, cudaFuncAttributeMaxDynamicSharedMemorySize, GEMM_SMEM);
        attr_set = true;
    }

    dim3 ggrid(EMB / 128, MDIM / 128);   // (8, 64)
    gemm_mma<<<ggrid, 256, GEMM_SMEM>>>(query, q_w, q_b, nullptr, 0);
    gemm_mma<<<ggrid, 256, GEMM_SMEM>>>(key,   k_w, k_b, nullptr, 1);
    gemm_mma<<<ggrid, 256, GEMM_SMEM>>>(value, v_w, v_b, nullptr, 2);

    attn_kernel<<<dim3(SEQ / 128, BATCH * HEADS), 128>>>();

    gemm_mma<<<ggrid, 256, GEMM_SMEM>>>(nullptr, out_w, out_b, out, 3);
}

// round 16
// speedup vs baseline: 3.4647x; 2.5256x over previous
#include <cuda_runtime.h>
#include <cuda_bf16.h>
#include <cstdint>

// Problem constants
#define BATCH 4
#define SEQ   2048
#define EMB   1024
#define HEADS 16
#define HDIM  64
#define MDIM  (BATCH * SEQ)   // 8192
#define SCALING 0.125f        // 64^-0.5

// Scratch — [B,H,S,D] layouts for Q/K/V, [B,S,E] for attn out
__device__ float g_Q[(size_t)BATCH * HEADS * SEQ * HDIM];
__device__ float g_K[(size_t)BATCH * HEADS * SEQ * HDIM];
__device__ float g_V[(size_t)BATCH * HEADS * SEQ * HDIM];
__device__ float g_attn[(size_t)BATCH * SEQ * EMB];

__device__ __forceinline__ uint32_t cvt_tf32(float x) {
    uint32_t r;
    asm("cvt.rna.tf32.f32 %0, %1;" : "=r"(r) : "f"(x));
    return r;
}

__device__ __forceinline__ void mma_16x8x8(float* c, const uint32_t* a, const uint32_t* b) {
    asm volatile(
        "mma.sync.aligned.m16n8k8.row.col.f32.tf32.tf32.f32 "
        "{%0,%1,%2,%3}, {%4,%5,%6,%7}, {%8,%9}, {%0,%1,%2,%3};"
        : "+f"(c[0]), "+f"(c[1]), "+f"(c[2]), "+f"(c[3])
        : "r"(a[0]), "r"(a[1]), "r"(a[2]), "r"(a[3]), "r"(b[0]), "r"(b[1]));
}

// ---------------------------------------------------------------------------
// mma.sync tf32 GEMM (unchanged from R7 WIN)
// ---------------------------------------------------------------------------
#define BK   32
#define PAD  36
#define STAGE_WORDS (128 * PAD)
#define GEMM_SMEM (4 * STAGE_WORDS * 4)

__global__ __launch_bounds__(256, 1)
void gemm_mma(const float* __restrict__ Ain, const float* __restrict__ W,
              const float* __restrict__ bias, float* __restrict__ outp, int which)
{
    extern __shared__ uint32_t sm[];
    uint32_t* As = sm;
    uint32_t* Bs = sm + 2 * STAGE_WORDS;

    const int tid  = threadIdx.x;
    const int warp = tid >> 5, lane = tid & 31;
    const int g = lane >> 2, t = lane & 3;
    const int wm = warp >> 2, wn = warp & 3;
    const int bm = blockIdx.y * 128, bn = blockIdx.x * 128;
    const float* A = (which == 3) ? g_attn : Ain;

    float4 ra[4], rb[4];
    #pragma unroll
    for (int i = 0; i < 4; i++) {
        const int l = tid + 256 * i, row = l >> 3, c4 = l & 7;
        ra[i] = *(const float4*)(A + (size_t)(bm + row) * EMB + c4 * 4);
        rb[i] = *(const float4*)(W + (size_t)(bn + row) * EMB + c4 * 4);
    }
    #pragma unroll
    for (int i = 0; i < 4; i++) {
        const int l = tid + 256 * i, row = l >> 3, c4 = l & 7;
        uint32_t* pa = As + row * PAD + c4 * 4;
        uint32_t* pb = Bs + row * PAD + c4 * 4;
        pa[0] = cvt_tf32(ra[i].x); pa[1] = cvt_tf32(ra[i].y);
        pa[2] = cvt_tf32(ra[i].z); pa[3] = cvt_tf32(ra[i].w);
        pb[0] = cvt_tf32(rb[i].x); pb[1] = cvt_tf32(rb[i].y);
        pb[2] = cvt_tf32(rb[i].z); pb[3] = cvt_tf32(rb[i].w);
    }
    __syncthreads();

    float acc[4][4][4];
    #pragma unroll
    for (int mf = 0; mf < 4; mf++)
        #pragma unroll
        for (int nf = 0; nf < 4; nf++)
            #pragma unroll
            for (int c = 0; c < 4; c++) acc[mf][nf][c] = 0.f;

    const int NKT = EMB / BK;

    for (int kt = 0; kt < NKT; kt++) {
        const int cur = kt & 1;
        const uint32_t* Ab = As + cur * STAGE_WORDS;
        const uint32_t* Bb = Bs + cur * STAGE_WORDS;

        if (kt + 1 < NKT) {
            const int k0 = (kt + 1) * BK;
            #pragma unroll
            for (int i = 0; i < 4; i++) {
                const int l = tid + 256 * i, row = l >> 3, c4 = l & 7;
                ra[i] = *(const float4*)(A + (size_t)(bm + row) * EMB + k0 + c4 * 4);
                rb[i] = *(const float4*)(W + (size_t)(bn + row) * EMB + k0 + c4 * 4);
            }
        }

        #pragma unroll
        for (int ks = 0; ks < 4; ks++) {
            const int kk = ks * 8;
            uint32_t af[4][4], bf[4][2];
            #pragma unroll
            for (int mf = 0; mf < 4; mf++) {
                const int m = wm * 64 + mf * 16;
                af[mf][0] = Ab[(m + g) * PAD + kk + t];
                af[mf][1] = Ab[(m + g + 8) * PAD + kk + t];
                af[mf][2] = Ab[(m + g) * PAD + kk + t + 4];
                af[mf][3] = Ab[(m + g + 8) * PAD + kk + t + 4];
            }
            #pragma unroll
            for (int nf = 0; nf < 4; nf++) {
                const int n = wn * 32 + nf * 8;
                bf[nf][0] = Bb[(n + g) * PAD + kk + t];
                bf[nf][1] = Bb[(n + g) * PAD + kk + t + 4];
            }
            #pragma unroll
            for (int mf = 0; mf < 4; mf++)
                #pragma unroll
                for (int nf = 0; nf < 4; nf++)
                    mma_16x8x8(acc[mf][nf], af[mf], bf[nf]);
        }

        if (kt + 1 < NKT) {
            __syncthreads();
            const int nxt = 1 - cur;
            uint32_t* Aw = As + nxt * STAGE_WORDS;
            uint32_t* Bw = Bs + nxt * STAGE_WORDS;
            #pragma unroll
            for (int i = 0; i < 4; i++) {
                const int l = tid + 256 * i, row = l >> 3, c4 = l & 7;
                uint32_t* pa = Aw + row * PAD + c4 * 4;
                uint32_t* pb = Bw + row * PAD + c4 * 4;
                pa[0] = cvt_tf32(ra[i].x); pa[1] = cvt_tf32(ra[i].y);
                pa[2] = cvt_tf32(ra[i].z); pa[3] = cvt_tf32(ra[i].w);
                pb[0] = cvt_tf32(rb[i].x); pb[1] = cvt_tf32(rb[i].y);
                pb[2] = cvt_tf32(rb[i].z); pb[3] = cvt_tf32(rb[i].w);
            }
            __syncthreads();
        }
    }

    #pragma unroll
    for (int nf = 0; nf < 4; nf++) {
        const int n = bn + wn * 32 + nf * 8 + t * 2;
        const float2 bv = *(const float2*)(bias + n);
        #pragma unroll
        for (int mf = 0; mf < 4; mf++) {
            const int m0 = bm + wm * 64 + mf * 16 + g;
            float2 v0, v1;
            v0.x = acc[mf][nf][0] + bv.x; v0.y = acc[mf][nf][1] + bv.y;
            v1.x = acc[mf][nf][2] + bv.x; v1.y = acc[mf][nf][3] + bv.y;
            if (which <= 2) {
                float* dst = (which == 0) ? g_Q : (which == 1) ? g_K : g_V;
                const int h = n >> 6, d0 = n & 63;
                const int b0r = m0 >> 11, s0 = m0 & 2047;
                const int b1r = (m0 + 8) >> 11, s1 = (m0 + 8) & 2047;
                *(float2*)(dst + (((size_t)(b0r * HEADS + h) * SEQ + s0) * HDIM + d0)) = v0;
                *(float2*)(dst + (((size_t)(b1r * HEADS + h) * SEQ + s1) * HDIM + d0)) = v1;
            } else {
                *(float2*)(outp + (size_t)m0 * EMB + n) = v0;
                *(float2*)(outp + (size_t)(m0 + 8) * EMB + n) = v1;
            }
        }
    }
}

// ---------------------------------------------------------------------------
// Flash attention on tensor cores (tf32 mma.sync), 128 q-rows per CTA.
// 8 warps as 4(m) x 2(n), warp tile 32x32. Key tiles of 64.
// S fragments -> smem -> per-row online softmax -> P (tf32 bits in place)
// -> PV MMA with V read via per-lane transposed B addressing.
// ---------------------------------------------------------------------------
#define APAD 68
#define ATTN_SMEM ((128*APAD + 64*APAD + 64*APAD + 128*APAD + 128) * 4)

__global__ __launch_bounds__(256, 1)
void attn_mma()
{
    extern __shared__ uint32_t sh[];
    uint32_t* Qs = sh;                       // [128][APAD]
    uint32_t* Ks = Qs + 128 * APAD;          // [64][APAD]
    uint32_t* Vs = Ks + 64 * APAD;           // [64][APAD]  ([key][d], tf32)
    uint32_t* Ss = Vs + 64 * APAD;           // [128][APAD] S (fp32) then P (tf32)
    float*    corr_s = (float*)(Ss + 128 * APAD);  // [128]

    const int tid  = threadIdx.x;
    const int warp = tid >> 5, lane = tid & 31;
    const int g = lane >> 2, t = lane & 3;
    const int wm = warp >> 1, wn = warp & 1;
    const int bh = blockIdx.y;
    const int q0 = blockIdx.x * 128;

    const float* Qg = g_Q + ((size_t)bh * SEQ + q0) * HDIM;
    const float* Kg = g_K + (size_t)bh * SEQ * HDIM;
    const float* Vg = g_V + (size_t)bh * SEQ * HDIM;

    // load Q tile (pre-scaled by SCALING, tf32)
    #pragma unroll
    for (int i = 0; i < 8; i++) {
        const int l = tid + 256 * i, row = l >> 4, c4 = l & 15;
        float4 v = *(const float4*)(Qg + row * HDIM + c4 * 4);
        uint32_t* p = Qs + row * APAD + c4 * 4;
        p[0] = cvt_tf32(v.x * SCALING); p[1] = cvt_tf32(v.y * SCALING);
        p[2] = cvt_tf32(v.z * SCALING); p[3] = cvt_tf32(v.w * SCALING);
    }

    float4 kr[4], vr[4];
    #pragma unroll
    for (int i = 0; i < 4; i++) {
        const int l = tid + 256 * i, row = l >> 4, c4 = l & 15;
        kr[i] = *(const float4*)(Kg + row * HDIM + c4 * 4);
        vr[i] = *(const float4*)(Vg + row * HDIM + c4 * 4);
    }
    #pragma unroll
    for (int i = 0; i < 4; i++) {
        const int l = tid + 256 * i, row = l >> 4, c4 = l & 15;
        uint32_t* pk = Ks + row * APAD + c4 * 4;
        uint32_t* pv = Vs + row * APAD + c4 * 4;
        pk[0] = cvt_tf32(kr[i].x); pk[1] = cvt_tf32(kr[i].y);
        pk[2] = cvt_tf32(kr[i].z); pk[3] = cvt_tf32(kr[i].w);
        pv[0] = cvt_tf32(vr[i].x); pv[1] = cvt_tf32(vr[i].y);
        pv[2] = cvt_tf32(vr[i].z); pv[3] = cvt_tf32(vr[i].w);
    }
    __syncthreads();

    float m_r = -1e30f, l_r = 0.f;   // softmax state (valid for tid<128)
    float oacc[2][4][4];
    #pragma unroll
    for (int mf = 0; mf < 2; mf++)
        #pragma unroll
        for (int nf = 0; nf < 4; nf++)
            #pragma unroll
            for (int c = 0; c < 4; c++) oacc[mf][nf][c] = 0.f;

    const int NT = SEQ / 64;  // 32 key tiles

    for (int kt = 0; kt < NT; kt++) {
        // prefetch next K/V tile into regs
        if (kt + 1 < NT) {
            const float* Kn = Kg + (size_t)(kt + 1) * 64 * HDIM;
            const float* Vn = Vg + (size_t)(kt + 1) * 64 * HDIM;
            #pragma unroll
            for (int i = 0; i < 4; i++) {
                const int l = tid + 256 * i, row = l >> 4, c4 = l & 15;
                kr[i] = *(const float4*)(Kn + row * HDIM + c4 * 4);
                vr[i] = *(const float4*)(Vn + row * HDIM + c4 * 4);
            }
        }

        // S = Q @ K^T  (warp tile 32x32, K-dim = 64 = 8 steps)
        float sfr[2][4][4];
        #pragma unroll
        for (int mf = 0; mf < 2; mf++)
            #pragma unroll
            for (int nf = 0; nf < 4; nf++)
                #pragma unroll
                for (int c = 0; c < 4; c++) sfr[mf][nf][c] = 0.f;

        #pragma unroll
        for (int ks = 0; ks < 8; ks++) {
            const int kk = ks * 8;
            uint32_t af[2][4], bf[4][2];
            #pragma unroll
            for (int mf = 0; mf < 2; mf++) {
                const int m = wm * 32 + mf * 16;
                af[mf][0] = Qs[(m + g) * APAD + kk + t];
                af[mf][1] = Qs[(m + g + 8) * APAD + kk + t];
                af[mf][2] = Qs[(m + g) * APAD + kk + t + 4];
                af[mf][3] = Qs[(m + g + 8) * APAD + kk + t + 4];
            }
            #pragma unroll
            for (int nf = 0; nf < 4; nf++) {
                const int n = wn * 32 + nf * 8;
                bf[nf][0] = Ks[(n + g) * APAD + kk + t];
                bf[nf][1] = Ks[(n + g) * APAD + kk + t + 4];
            }
            #pragma unroll
            for (int mf = 0; mf < 2; mf++)
                #pragma unroll
                for (int nf = 0; nf < 4; nf++)
                    mma_16x8x8(sfr[mf][nf], af[mf], bf[nf]);
        }

        // spill S fragments to smem (fp32)
        #pragma unroll
        for (int mf = 0; mf < 2; mf++) {
            const int r0 = wm * 32 + mf * 16 + g;
            #pragma unroll
            for (int nf = 0; nf < 4; nf++) {
                const int cidx = wn * 32 + nf * 8 + t * 2;
                float2 v0, v1;
                v0.x = sfr[mf][nf][0]; v0.y = sfr[mf][nf][1];
                v1.x = sfr[mf][nf][2]; v1.y = sfr[mf][nf][3];
                *(float2*)(Ss + r0 * APAD + cidx) = v0;
                *(float2*)(Ss + (r0 + 8) * APAD + cidx) = v1;
            }
        }
        __syncthreads();

        // per-row online softmax; write P (tf32 bits) in place
        if (tid < 128) {
            float s[64];
            const float4* srow = (const float4*)(Ss + tid * APAD);
            #pragma unroll
            for (int i = 0; i < 16; i++) {
                float4 v = srow[i];
                s[4*i+0] = v.x; s[4*i+1] = v.y; s[4*i+2] = v.z; s[4*i+3] = v.w;
            }
            float tmax = m_r;
            #pragma unroll
            for (int j = 0; j < 64; j++) tmax = fmaxf(tmax, s[j]);
            const float corr = __expf(m_r - tmax);
            float sum = 0.f;
            uint32_t* prow = Ss + tid * APAD;
            #pragma unroll
            for (int j = 0; j < 64; j++) {
                const float e = __expf(s[j] - tmax);
                sum += e;
                prow[j] = cvt_tf32(e);
            }
            l_r = l_r * corr + sum;
            m_r = tmax;
            corr_s[tid] = corr;
        }
        __syncthreads();

        // rescale O by corr
        #pragma unroll
        for (int mf = 0; mf < 2; mf++) {
            const int r0 = wm * 32 + mf * 16 + g;
            const float c0 = corr_s[r0];
            const float c1 = corr_s[r0 + 8];
            #pragma unroll
            for (int nf = 0; nf < 4; nf++) {
                oacc[mf][nf][0] *= c0; oacc[mf][nf][1] *= c0;
                oacc[mf][nf][2] *= c1; oacc[mf][nf][3] *= c1;
            }
        }

        // O += P @ V  (K-dim = 64 keys = 8 steps; B = V^T via addressing)
        #pragma unroll
        for (int ks = 0; ks < 8; ks++) {
            const int kk = ks * 8;
            uint32_t af[2][4], bf[4][2];
            #pragma unroll
            for (int mf = 0; mf < 2; mf++) {
                const int m = wm * 32 + mf * 16;
                af[mf][0] = Ss[(m + g) * APAD + kk + t];
                af[mf][1] = Ss[(m + g + 8) * APAD + kk + t];
                af[mf][2] = Ss[(m + g) * APAD + kk + t + 4];
                af[mf][3] = Ss[(m + g + 8) * APAD + kk + t + 4];
            }
            #pragma unroll
            for (int nf = 0; nf < 4; nf++) {
                const int n = wn * 32 + nf * 8;
                bf[nf][0] = Vs[(kk + t) * APAD + n + g];
                bf[nf][1] = Vs[(kk + t + 4) * APAD + n + g];
            }
            #pragma unroll
            for (int mf = 0; mf < 2; mf++)
                #pragma unroll
                for (int nf = 0; nf < 4; nf++)
                    mma_16x8x8(oacc[mf][nf], af[mf], bf[nf]);
        }
        __syncthreads();   // everyone done with Ks/Vs/Ss

        // stage next K/V tile
        if (kt + 1 < NT) {
            #pragma unroll
            for (int i = 0; i < 4; i++) {
                const int l = tid + 256 * i, row = l >> 4, c4 = l & 15;
                uint32_t* pk = Ks + row * APAD + c4 * 4;
                uint32_t* pv = Vs + row * APAD + c4 * 4;
                pk[0] = cvt_tf32(kr[i].x); pk[1] = cvt_tf32(kr[i].y);
                pk[2] = cvt_tf32(kr[i].z); pk[3] = cvt_tf32(kr[i].w);
                pv[0] = cvt_tf32(vr[i].x); pv[1] = cvt_tf32(vr[i].y);
                pv[2] = cvt_tf32(vr[i].z); pv[3] = cvt_tf32(vr[i].w);
            }
            __syncthreads();
        }
    }

    // final 1/l and output
    if (tid < 128) corr_s[tid] = 1.f / l_r;
    __syncthreads();

    const int b = bh >> 4, h = bh & 15;
    #pragma unroll
    for (int mf = 0; mf < 2; mf++) {
        const int r0 = wm * 32 + mf * 16 + g;
        const float i0 = corr_s[r0];
        const float i1 = corr_s[r0 + 8];
        float* o0 = g_attn + ((size_t)(b * SEQ + q0 + r0) * EMB) + h * HDIM;
        float* o1 = g_attn + ((size_t)(b * SEQ + q0 + r0 + 8) * EMB) + h * HDIM;
        #pragma unroll
        for (int nf = 0; nf < 4; nf++) {
            const int cidx = wn * 32 + nf * 8 + t * 2;
            float2 v0, v1;
            v0.x = oacc[mf][nf][0] * i0; v0.y = oacc[mf][nf][1] * i0;
            v1.x = oacc[mf][nf][2] * i1; v1.y = oacc[mf][nf][3] * i1;
            *(float2*)(o0 + cidx) = v0;
            *(float2*)(o1 + cidx) = v1;
        }
    }
}

// ---------------------------------------------------------------------------
// Launch
// ---------------------------------------------------------------------------
extern "C" void kernel_launch(void* const* d_in, const int* in_sizes, int n_in,
                              void* d_out, int out_size)
{
    const float* query = (const float*)d_in[0];
    const float* key   = (const float*)d_in[1];
    const float* value = (const float*)d_in[2];
    const float* q_w   = (const float*)d_in[3];
    const float* q_b   = (const float*)d_in[4];
    const float* k_w   = (const float*)d_in[5];
    const float* k_b   = (const float*)d_in[6];
    const float* v_w   = (const float*)d_in[7];
    const float* v_b   = (const float*)d_in[8];
    const float* out_w = (const float*)d_in[9];
    const float* out_b = (const float*)d_in[10];
    float* out = (float*)d_out;

    static bool attr_set = false;
    if (!attr_set) {
        cudaFuncSetAttribute(gemm_mma, cudaFuncAttributeMaxDynamicSharedMemorySize, GEMM_SMEM);
        cudaFuncSetAttribute(attn_mma, cudaFuncAttributeMaxDynamicSharedMemorySize, ATTN_SMEM);
        attr_set = true;
    }

    dim3 ggrid(EMB / 128, MDIM / 128);   // (8, 64)
    gemm_mma<<<ggrid, 256, GEMM_SMEM>>>(query, q_w, q_b, nullptr, 0);
    gemm_mma<<<ggrid, 256, GEMM_SMEM>>>(key,   k_w, k_b, nullptr, 1);
    gemm_mma<<<ggrid, 256, GEMM_SMEM>>>(value, v_w, v_b, nullptr, 2);

    attn_mma<<<dim3(SEQ / 128, BATCH * HEADS), 256, ATTN_SMEM>>>();

    gemm_mma<<<ggrid, 256, GEMM_SMEM>>>(nullptr, out_w, out_b, out, 3);
}